// round 7
// baseline (speedup 1.0000x reference)
#include <cuda_runtime.h>
#include <cuda_bf16.h>

// out[b,m] = dot(inputs[b,m,:], W[m,:]) + bias[m]
// B=1024, M=2048, I=128 (fp32). HBM-streaming: ~1.08 GB traffic.
//
// R4: 8 rows per warp (two 4-row groups, 8 lanes per row), 16 front-batched
// LDG.128 per warp (MLP=16), __ldcs streaming loads for the read-once input,
// __ldg for the L2-resident weights. Two 3-level shfl trees reduce all 8 rows.

#ifndef B_DIM
#define B_DIM 1024
#endif
#ifndef M_DIM
#define M_DIM 2048
#endif
#ifndef I_DIM
#define I_DIM 128
#endif

static constexpr int WARPS_PER_BLOCK = 8;
static constexpr int THREADS_PER_BLOCK = WARPS_PER_BLOCK * 32;
static constexpr int ROWS_PER_WARP = 8;       // two groups of 4 rows
static constexpr int F4_PER_ROW = I_DIM / 4;  // 32 float4 per row

__device__ __forceinline__ float dot4(const float4 a, const float4 w) {
    float s = a.x * w.x;
    s = fmaf(a.y, w.y, s);
    s = fmaf(a.z, w.z, s);
    s = fmaf(a.w, w.w, s);
    return s;
}

__global__ __launch_bounds__(THREADS_PER_BLOCK)
void diag_linear_kernel(const float4* __restrict__ inp4,   // [B*M*32] float4
                        const float4* __restrict__ w4,     // [M*32] float4
                        const float* __restrict__ bias,    // [M]
                        float* __restrict__ out)           // [B*M]
{
    const int lane = threadIdx.x & 31;
    const int r = lane >> 3;          // row within 4-row group
    const int c = lane & 7;           // chunk within row

    const long long warp = (long long)blockIdx.x * WARPS_PER_BLOCK + (threadIdx.x >> 5);
    const long long row0 = warp * ROWS_PER_WARP;

    const long long rowA = row0 + r;        // group A: rows row0..row0+3
    const long long rowB = row0 + 4 + r;    // group B: rows row0+4..row0+7

    // row0 is 8-aligned; M_DIM pow2 -> 8-row group never crosses the M boundary.
    const int mA = (int)(rowA & (long long)(M_DIM - 1));
    const int mB = (int)(rowB & (long long)(M_DIM - 1));

    const float4* __restrict__ iaA = inp4 + rowA * F4_PER_ROW + c;
    const float4* __restrict__ iaB = inp4 + rowB * F4_PER_ROW + c;
    const float4* __restrict__ waA = w4 + (long long)mA * F4_PER_ROW + c;
    const float4* __restrict__ waB = w4 + (long long)mB * F4_PER_ROW + c;

    // 16 independent LDG.128 issued up-front (MLP_p1 = 16).
    // Inputs: read-once -> streaming (evict-first). Weights: L2-hot -> __ldg.
    const float4 a0 = __ldcs(&iaA[0 * 8]);
    const float4 a1 = __ldcs(&iaA[1 * 8]);
    const float4 a2 = __ldcs(&iaA[2 * 8]);
    const float4 a3 = __ldcs(&iaA[3 * 8]);
    const float4 b0 = __ldcs(&iaB[0 * 8]);
    const float4 b1 = __ldcs(&iaB[1 * 8]);
    const float4 b2 = __ldcs(&iaB[2 * 8]);
    const float4 b3 = __ldcs(&iaB[3 * 8]);
    const float4 u0 = __ldg(&waA[0 * 8]);
    const float4 u1 = __ldg(&waA[1 * 8]);
    const float4 u2 = __ldg(&waA[2 * 8]);
    const float4 u3 = __ldg(&waA[3 * 8]);
    const float4 v0 = __ldg(&waB[0 * 8]);
    const float4 v1 = __ldg(&waB[1 * 8]);
    const float4 v2 = __ldg(&waB[2 * 8]);
    const float4 v3 = __ldg(&waB[3 * 8]);

    float sA = dot4(a0, u0);
    sA += dot4(a1, u1);
    sA += dot4(a2, u2);
    sA += dot4(a3, u3);

    float sB = dot4(b0, v0);
    sB += dot4(b1, v1);
    sB += dot4(b2, v2);
    sB += dot4(b3, v3);

    // 3-level butterfly within each 8-lane group; reduces 4 rows per tree.
    sA += __shfl_xor_sync(0xFFFFFFFFu, sA, 4);
    sB += __shfl_xor_sync(0xFFFFFFFFu, sB, 4);
    sA += __shfl_xor_sync(0xFFFFFFFFu, sA, 2);
    sB += __shfl_xor_sync(0xFFFFFFFFu, sB, 2);
    sA += __shfl_xor_sync(0xFFFFFFFFu, sA, 1);
    sB += __shfl_xor_sync(0xFFFFFFFFu, sB, 1);

    // Lanes 0,8,16,24 hold valid sums: 8 consecutive floats per warp, coalesced.
    if (c == 0) {
        out[rowA] = sA + __ldg(&bias[mA]);
        out[rowB] = sB + __ldg(&bias[mB]);
    }
}

extern "C" void kernel_launch(void* const* d_in, const int* in_sizes, int n_in,
                              void* d_out, int out_size)
{
    const float4* inp4 = (const float4*)d_in[0];  // inputs [B, M, I] fp32
    const float4* w4   = (const float4*)d_in[1];  // Rk_weight [M, I] fp32
    const float*  bias = (const float*)d_in[2];   // bias [M] fp32
    float* out = (float*)d_out;                   // [B, M] fp32

    const long long total_rows = (long long)B_DIM * M_DIM;          // 2,097,152
    const long long warps = total_rows / ROWS_PER_WARP;             // 262,144
    const int grid = (int)((warps + WARPS_PER_BLOCK - 1) / WARPS_PER_BLOCK); // 32,768

    diag_linear_kernel<<<grid, THREADS_PER_BLOCK>>>(inp4, w4, bias, out);
}